// round 16
// baseline (speedup 1.0000x reference)
#include <cuda_runtime.h>
#include <math.h>
#include <float.h>

#define B    2
#define P    19248
#define NC   100
#define NK   20
#define HP   138
#define HIMG 550
#define DM   32
#define NBIN 1024
#define CAND 1024
#define NBLK 148
#define NTH  1024
#define SF   (138.0f/550.0f)
#define MAXFR 5
#define MAXYR 4
#define NPAIR (NC*(NC-1)/2)       /* 4950 */
#define A1C  (2*NC-1)             /* 199 */

__device__ float d_confp[B*P];                      // fallback path only
__device__ unsigned long long d_cand[B*CAND];
__device__ unsigned d_candcnt[B];
__device__ unsigned d_total[B];
__device__ float d_iou[B*NC*NC];
__device__ __align__(16) unsigned d_ioumax[B*NC];   // float-as-uint max, values >= 0
__device__ float d_ae[B];
__device__ double d_var_part[8];
__device__ unsigned d_done;
__device__ unsigned bar_count;
__device__ volatile unsigned bar_gen;

// grid-wide barrier: grid(148) <= #SMs, 1 block/SM => all co-resident.
__device__ __forceinline__ void gridsync() {
    __syncthreads();
    if (threadIdx.x == 0) {
        __threadfence();
        unsigned gen = bar_gen;
        unsigned arrived = atomicAdd(&bar_count, 1u);
        if (arrived == (unsigned)gridDim.x - 1u) {
            bar_count = 0u;
            __threadfence();
            bar_gen = gen + 1u;
        } else {
            while (bar_gen == gen) { }
            __threadfence();
        }
    }
    __syncthreads();
}

__device__ __forceinline__ void l2prefetch(const void* p) {
    asm volatile("prefetch.global.L2 [%0];" :: "l"(p));
}

// triangular pair decode: t in [0, NPAIR) -> (i, j), j > i
__device__ __forceinline__ void pairDecode(int t, int& i, int& j) {
    int ii = (int)(((float)A1C - sqrtf((float)(A1C*A1C) - 8.0f*(float)t)) * 0.5f);
    if (ii < 0) ii = 0;
    if (ii > NC-2) ii = NC-2;
    while (ii > 0 && ii*(A1C-ii)/2 > t) --ii;
    while (ii < NC-2 && (ii+1)*(A1C-(ii+1))/2 <= t) ++ii;
    i = ii;
    j = ii + 1 + (t - ii*(A1C-ii)/2);
}

__global__ void __launch_bounds__(NTH, 1)
fusedK(const float* __restrict__ original, const float* __restrict__ loc,
       const float* __restrict__ conf, const float* __restrict__ mask,
       const float* __restrict__ proto, float* __restrict__ out)
{
    __shared__ __align__(16) union {
        struct { unsigned hist[NBIN]; } a1;
        struct { unsigned long long cand[CAND]; } a2;
        struct { float ax[NC*32]; float ay[NC*32]; float gsum[NC]; float loc4[NC*4]; } b;
        struct { float m[2*NC]; } c;
        struct { float fc[2*MAXFR*HP]; float vrow[2*MAXYR*HP]; } d;
    } u;
    __shared__ float s_top_conf[B*NC];
    __shared__ int   s_top_idx[B*NC];
    __shared__ __align__(16) float s_km[B*NK*DM];
    __shared__ float s_kl[B*NK*4];
    __shared__ float s_krw[B*NK*2];
    __shared__ float s_kc[B*NK];
    __shared__ int   s_keep[B*NK];
    __shared__ float s_red[32];
    __shared__ unsigned s_wu[32];
    __shared__ int   s_T;

    const int tid  = threadIdx.x;
    const int warp = tid >> 5, lane = tid & 31;
    const int bid  = blockIdx.x;
    const int bb   = bid & 1;            // this block's batch for phase B

    // ===== Phase A: full selection on blocks 0,1 (one block per batch); rest prefetch =====
    if (bid < B) {
        int b = bid;
        u.a1.hist[tid] = 0u;
        __syncthreads();
        // pass 1: sigmoid + smem histogram
        for (int p = tid; p < P; p += NTH) {
            float2 c2 = *(const float2*)(conf + (size_t)(b*P + p)*2);
            float v = 1.0f / (1.0f + expf(c2.x - c2.y));
            int bucket = min(NBIN-1, max(0, (int)(v * (float)NBIN)));
            atomicAdd(&u.a1.hist[bucket], 1u);
        }
        __syncthreads();
        // shuffle-based suffix scan over 1024 bins
        unsigned v = u.a1.hist[tid];
        #pragma unroll
        for (int off = 1; off < 32; off <<= 1) {
            unsigned t = __shfl_down_sync(0xffffffffu, v, off);
            if (lane + off < 32) v += t;
        }
        if (lane == 0) s_wu[warp] = v;
        __syncthreads();
        if (tid < 32) {
            unsigned wv = s_wu[tid];
            unsigned a = wv;
            #pragma unroll
            for (int off = 1; off < 32; off <<= 1) {
                unsigned t = __shfl_down_sync(0xffffffffu, a, off);
                if (lane + off < 32) a += t;
            }
            s_wu[tid] = a - wv;              // exclusive suffix over warps > tid
        }
        __syncthreads();
        unsigned suf = v + s_wu[warp];
        u.a1.hist[tid] = suf;
        __syncthreads();
        if (suf >= NC && (tid == NBIN-1 || u.a1.hist[tid+1] < NC)) s_T = tid;
        __syncthreads();
        int T = s_T;
        unsigned total = u.a1.hist[T];
        if (tid == 0) d_total[b] = total;
        if (total <= CAND) {
            // pass 2: compact (recompute sigmoid — bit-identical expression)
            for (int p = tid; p < P; p += NTH) {
                float2 c2 = *(const float2*)(conf + (size_t)(b*P + p)*2);
                float vv = 1.0f / (1.0f + expf(c2.x - c2.y));
                int bucket = min(NBIN-1, max(0, (int)(vv * (float)NBIN)));
                if (bucket >= T) {
                    unsigned pos = atomicAdd(&d_candcnt[b], 1u);
                    d_cand[b*CAND + pos] = ((unsigned long long)__float_as_uint(vv) << 32)
                                         | (unsigned long long)(0xFFFFFFFFu - (unsigned)p);
                }
            }
        } else {
            // pathological: materialize confp for the redundant fallback scans
            for (int p = tid; p < P; p += NTH) {
                float2 c2 = *(const float2*)(conf + (size_t)(b*P + p)*2);
                d_confp[b*P + p] = 1.0f / (1.0f + expf(c2.x - c2.y));
            }
        }
    } else {
        // prefetch original (7.26MB) + proto (4.87MB) + loc (0.31MB) into L2
        const size_t lines1 = ((size_t)B*3*HIMG*HIMG*4) >> 7;
        const size_t lines2 = ((size_t)B*HP*HP*DM*4) >> 7;
        const size_t lines3 = ((size_t)B*P*4*4) >> 7;
        size_t start = (size_t)(bid - B) * NTH + tid;
        size_t stride = (size_t)(NBLK - B) * NTH;
        const char* o = (const char*)original;
        const char* q = (const char*)proto;
        const char* l = (const char*)loc;
        for (size_t i = start; i < lines1; i += stride) l2prefetch(o + (i << 7));
        for (size_t i = start; i < lines2; i += stride) l2prefetch(q + (i << 7));
        for (size_t i = start; i < lines3; i += stride) l2prefetch(l + (i << 7));
    }
    gridsync();

    // ===== Phase A2b: redundant rank on EVERY block (both batches, cheap) =====
    for (int cb = 0; cb < B; cb++) {
        unsigned total = d_total[cb];
        if (total <= CAND) {
            int cnt = (int)d_candcnt[cb];
            for (int i = tid; i < cnt; i += NTH) u.a2.cand[i] = d_cand[cb*CAND + i];
            __syncthreads();
            if (tid < cnt) {
                unsigned long long mykey = u.a2.cand[tid];
                int rank = 0;
                #pragma unroll 4
                for (int c2 = 0; c2 < cnt; c2++)
                    rank += (u.a2.cand[c2] > mykey) ? 1 : 0;
                if (rank < NC) {
                    s_top_conf[cb*NC + rank] = __uint_as_float((unsigned)(mykey >> 32));
                    s_top_idx[cb*NC + rank]  = (int)(0xFFFFFFFFu - (unsigned)(mykey & 0xFFFFFFFFull));
                }
            }
            __syncthreads();
        } else {
            // pathological fallback: redundant non-destructive iterative max (all blocks)
            unsigned long long prev = 0xFFFFFFFFFFFFFFFFull;
            for (int it = 0; it < NC; it++) {
                unsigned long long best = 0ull;
                for (int p = tid; p < P; p += NTH) {
                    float v = d_confp[cb*P + p];
                    unsigned long long key = ((unsigned long long)__float_as_uint(v) << 32)
                                           | (unsigned long long)(0xFFFFFFFFu - (unsigned)p);
                    if (key < prev && key > best) best = key;
                }
                #pragma unroll
                for (int off = 16; off > 0; off >>= 1) {
                    unsigned long long o = __shfl_down_sync(0xffffffffu, best, off);
                    if (o > best) best = o;
                }
                if (lane == 0) u.a2.cand[warp] = best;
                __syncthreads();
                if (tid < 32) {
                    best = u.a2.cand[tid];
                    #pragma unroll
                    for (int off = 16; off > 0; off >>= 1) {
                        unsigned long long o = __shfl_down_sync(0xffffffffu, best, off);
                        if (o > best) best = o;
                    }
                    if (tid == 0) {
                        s_top_conf[cb*NC + it] = __uint_as_float((unsigned)(best >> 32));
                        s_top_idx[cb*NC + it]  = (int)(0xFFFFFFFFu - (unsigned)(best & 0xFFFFFFFFull));
                        u.a2.cand[0] = best;
                    }
                }
                __syncthreads();
                prev = u.a2.cand[0];
                __syncthreads();
            }
        }
    }

    // ===== Phase B: pairwise IoU for batch bb, 74-block pair partitions =====
    {
        if (tid < NC*4) {
            int box = tid >> 2, c = tid & 3;
            int gi = s_top_idx[bb*NC + box];
            u.b.loc4[tid] = loc[((size_t)bb*P + gi)*4 + c];
        }
        __syncthreads();
        for (int t = tid; t < NC*32; t += NTH) {
            int box = t >> 5, e = t & 31;
            float s = (e + 0.5f) / 32.0f;
            float dx = (s - u.b.loc4[box*4+0]) / (u.b.loc4[box*4+2] + 1e-4f);
            float dy = (s - u.b.loc4[box*4+1]) / (u.b.loc4[box*4+3] + 1e-4f);
            u.b.ax[t] = expf(-0.5f * dx * dx);
            u.b.ay[t] = expf(-0.5f * dy * dy);
        }
        __syncthreads();
        if (tid < NC) {
            float sx = 0.f, sy = 0.f;
            #pragma unroll
            for (int e = 0; e < 32; e++) { sx += u.b.ax[tid*32+e]; sy += u.b.ay[tid*32+e]; }
            u.b.gsum[tid] = sx * sy;
        }
        __syncthreads();
        const int pb = bid >> 1;                 // 0..73 within batch partition
        for (int t = pb*32 + warp; t < NPAIR; t += 74*32) {
            int i, j;
            pairDecode(t, i, j);
            float gix = u.b.ax[i*32 + lane];
            float axj = u.b.ax[j*32 + lane];
            float acc = 0.f;
            #pragma unroll
            for (int y = 0; y < 32; y++)
                acc += fminf(u.b.ay[i*32 + y] * gix, u.b.ay[j*32 + y] * axj);
            #pragma unroll
            for (int off = 16; off > 0; off >>= 1)
                acc += __shfl_down_sync(0xffffffffu, acc, off);
            if (lane == 0) {
                float denom = u.b.gsum[i] + u.b.gsum[j] - acc;
                float iouv = acc / denom;
                d_iou[(bb*NC + i)*NC + j] = iouv;
                atomicMax(&d_ioumax[bb*NC + j], __float_as_uint(iouv));
            }
        }
    }
    gridsync();

    // ===== Phase C: keep-20 + gathers (all blocks, cheap); AE on blocks 0,1 =====
    {
        // reset d_candcnt (consumed in A2b before the barrier)
        if (bid == 0 && tid < B) d_candcnt[tid] = 0u;
        // col-max precomputed via atomicMax in B
        if (tid < 2*NC) u.c.m[tid] = __uint_as_float(d_ioumax[tid]);
        __syncthreads();
        // rank-by-counting ascending (m, j)
        if (tid < 2*NC) {
            int cb = tid / NC, j = tid % NC;
            float m = u.c.m[tid];
            int rank = 0;
            #pragma unroll 4
            for (int j2 = 0; j2 < NC; j2++) {
                float m2 = u.c.m[cb*NC + j2];
                rank += (m2 < m || (m2 == m && j2 < j)) ? 1 : 0;
            }
            if (rank < NK) s_keep[cb*NK + rank] = j;
        }
        __syncthreads();
        if (tid < B*NK) {
            int cb = tid / NK;
            int j = s_keep[tid];
            int gi = s_top_idx[cb*NC + j];
            s_kc[tid] = s_top_conf[cb*NC + j];
            #pragma unroll
            for (int c = 0; c < 4; c++)
                s_kl[tid*4 + c] = loc[((size_t)cb*P + gi)*4 + c];
            s_krw[tid*2 + 0] = 1.0f / (s_kl[tid*4 + 2] + 1e-4f);
            s_krw[tid*2 + 1] = 1.0f / (s_kl[tid*4 + 3] + 1e-4f);
        }
        __syncthreads();
        for (int t = tid; t < B*NK*DM; t += NTH) {
            int cb = t / (NK*DM);
            int k = (t / DM) % NK, c = t % DM;
            int gi = s_top_idx[cb*NC + s_keep[cb*NK + k]];
            s_km[t] = mask[((size_t)cb*P + gi)*DM + c];
        }
        __syncthreads();
        if (bid < B) {
            int b = bid;
            float acc = 0.f;
            for (int t = tid; t < NK*NC; t += NTH) {
                int k = t / NC, j = t % NC;
                int ik = s_keep[b*NK + k];
                if (j > ik) {
                    float l0 = s_kl[(b*NK + k)*4 + 0], l1 = s_kl[(b*NK + k)*4 + 1];
                    float l2 = s_kl[(b*NK + k)*4 + 2], l3 = s_kl[(b*NK + k)*4 + 3];
                    float ael = 0.25f * (l0*l0 + l1*l1 + l2*l2 + l3*l3);
                    acc += ael * s_top_conf[b*NC + ik] * s_top_conf[b*NC + j]
                               * d_iou[(b*NC + ik)*NC + j];
                }
            }
            #pragma unroll
            for (int off = 16; off > 0; off >>= 1) acc += __shfl_down_sync(0xffffffffu, acc, off);
            if (lane == 0) s_red[warp] = acc;
            __syncthreads();
            if (tid < 32) {
                acc = s_red[tid];
                #pragma unroll
                for (int off = 16; off > 0; off >>= 1) acc += __shfl_down_sync(0xffffffffu, acc, off);
                if (tid == 0) d_ae[b] = acc / (float)(B*NC*NC);
            }
        }
        __syncthreads();
    }

    // ===== Phase D: per-strip fconf + separable bilinear + variance (R12 form) =====
    {
        int y0 = bid * HIMG / NBLK, y1 = (bid + 1) * HIMG / NBLK;
        float fyMin = (y0 + 0.5f)*SF - 0.5f;
        float fyMax = (y1 - 0.5f)*SF - 0.5f;
        int fr0 = max((int)floorf(fyMin), 0);
        int fr1 = min((int)floorf(fyMax) + 1, HP-1);
        int nfr = fr1 - fr0 + 1;                      // <= MAXFR
        for (int t = tid; t < B*nfr*HP; t += NTH) {
            int b = t / (nfr*HP);
            int r = (t / HP) % nfr;
            int w = t % HP;
            int fh = fr0 + r;
            const float4* pr4 = (const float4*)(proto + ((size_t)(b*HP + fh)*HP + w) * DM);
            const float4* km4 = (const float4*)(s_km + b*NK*DM);
            float acc[NK];
            #pragma unroll
            for (int k = 0; k < NK; k++) acc[k] = 0.f;
            #pragma unroll
            for (int c4 = 0; c4 < 8; c4++) {
                float4 p4 = pr4[c4];
                #pragma unroll
                for (int k = 0; k < NK; k++) {
                    float4 m4 = km4[k*8 + c4];
                    acc[k] += p4.x*m4.x + p4.y*m4.y + p4.z*m4.z + p4.w*m4.w;
                }
            }
            float xs = (w + 0.5f) * (1.0f/(float)HP);
            float ys = (fh + 0.5f) * (1.0f/(float)HP);
            float s1 = 0.f, s2 = 0.f;
            #pragma unroll
            for (int k = 0; k < NK; k++) {
                float e = __expf(-acc[k]);
                float sig = __fdividef(1.0f, 1.0f + e);
                float cx = s_kl[(b*NK+k)*4+0], cy = s_kl[(b*NK+k)*4+1];
                float rw = s_krw[(b*NK+k)*2+0], rh = s_krw[(b*NK+k)*2+1];
                float dx = (xs - cx) * rw;
                float dy = (ys - cy) * rh;
                float g = __expf(-0.5f * (dx*dx + dy*dy));
                float mc = sig * g * s_kc[b*NK + k];
                s1 += mc;
                s2 = fmaf(mc, mc, s2);
            }
            float fc = 1.0f - __fdividef(s2, s1 + 1e-6f);
            if (fc != fc) fc = 0.f;
            u.d.fc[(b*MAXFR + r)*HP + w] = fc;
        }
        __syncthreads();
        // vertical interpolation rows: vrow[b][rr][xc], rr in [0, y1-y0)
        int nyr = y1 - y0;                            // <= MAXYR
        for (int t = tid; t < B*nyr*HP; t += NTH) {
            int b = t / (nyr*HP);
            int rr = (t / HP) % nyr;
            int xc = t % HP;
            int y = y0 + rr;
            float fy = (y + 0.5f)*SF - 0.5f;
            float fy0 = floorf(fy);
            float ty = fy - fy0;
            int yy0 = (int)fy0;
            int y0c = min(max(yy0, 0), HP-1), y1c = min(max(yy0+1, 0), HP-1);
            int r0i = y0c - fr0, r1i = y1c - fr0;
            const float* fb = &u.d.fc[b*MAXFR*HP];
            float a = fb[r0i*HP + xc], bv = fb[r1i*HP + xc];
            u.d.vrow[(b*MAXYR + rr)*HP + xc] = a + ty*(bv - a);
        }
        __syncthreads();
        float acc = 0.f;
        {
            int npix2 = (nyr * HIMG) >> 1;            // always even
            int gbase = y0 * HIMG;
            for (int idx2 = tid; idx2 < npix2; idx2 += NTH) {
                int g = gbase + (idx2 << 1);
                int y = g / HIMG, x = g - y * HIMG;   // x even, x+1 in same row
                int rr = y - y0;
                const float* v0 = &u.d.vrow[(0*MAXYR + rr)*HP];
                const float* v1 = &u.d.vrow[(1*MAXYR + rr)*HP];
                float rA0, rA1, rB0, rB1;
                #pragma unroll
                for (int px = 0; px < 2; px++) {
                    float fx = (x + px + 0.5f)*SF - 0.5f;
                    float fx0 = floorf(fx);
                    float tx = fx - fx0;
                    int x0 = (int)fx0;
                    int x0c = min(max(x0, 0), HP-1), x1c = min(max(x0+1, 0), HP-1);
                    float a0 = v0[x0c], b0 = v0[x1c];
                    float a1 = v1[x0c], b1 = v1[x1c];
                    float r0 = a0 + tx*(b0 - a0);
                    float r1 = a1 + tx*(b1 - a1);
                    if (px == 0) { rA0 = r0; rA1 = r1; } else { rB0 = r0; rB1 = r1; }
                }
                float totA = rA0 + rA1, totB = rB0 + rB1;
                float invA  = __fdividef(1.0f, totA);
                float invB  = __fdividef(1.0f, totB);
                float invAe = __fdividef(1.0f, totA + 1e-6f);
                float invBe = __fdividef(1.0f, totB + 1e-6f);
                #pragma unroll
                for (int c = 0; c < 3; c++) {
                    float2 o0 = *(const float2*)(original + (size_t)(0*3 + c)*HIMG*HIMG + g);
                    float2 o1 = *(const float2*)(original + (size_t)(1*3 + c)*HIMG*HIMG + g);
                    float wmA = (o0.x*rA0 + o1.x*rA1) * invA;
                    float dA0 = o0.x - wmA, dA1 = o1.x - wmA;
                    acc += (dA0*dA0*rA0 + dA1*dA1*rA1) * invAe;
                    float wmB = (o0.y*rB0 + o1.y*rB1) * invB;
                    float dB0 = o0.y - wmB, dB1 = o1.y - wmB;
                    acc += (dB0*dB0*rB0 + dB1*dB1*rB1) * invBe;
                }
            }
        }
        #pragma unroll
        for (int off = 16; off > 0; off >>= 1) acc += __shfl_down_sync(0xffffffffu, acc, off);
        if (lane == 0) s_red[warp] = acc;
        __syncthreads();
        if (tid < 32) {
            acc = s_red[tid];
            #pragma unroll
            for (int off = 16; off > 0; off >>= 1) acc += __shfl_down_sync(0xffffffffu, acc, off);
            if (tid == 0) {
                atomicAdd(&d_var_part[bid & 7], (double)acc);
                __threadfence();
                unsigned ticket = atomicAdd(&d_done, 1u);
                if (ticket == (unsigned)gridDim.x - 1u) {
                    __threadfence();
                    double vs = 0.0;
                    #pragma unroll
                    for (int i = 0; i < 8; i++) { vs += d_var_part[i]; d_var_part[i] = 0.0; }
                    out[0] = (float)(vs / (double)HP * (double)B);
                    out[1] = d_ae[0] + d_ae[1];
                    uint4 z = make_uint4(0u, 0u, 0u, 0u);
                    for (int i = 0; i < (B*NC)/4; i++)           // reset for replay
                        ((uint4*)d_ioumax)[i] = z;
                    d_done = 0u;
                }
            }
        }
    }
}

extern "C" void kernel_launch(void* const* d_in, const int* in_sizes, int n_in,
                              void* d_out, int out_size) {
    const float* original = (const float*)d_in[0];
    const float* loc      = (const float*)d_in[1];
    const float* conf     = (const float*)d_in[2];
    const float* mask     = (const float*)d_in[3];
    const float* proto    = (const float*)d_in[4];
    float* out = (float*)d_out;

    fusedK<<<NBLK, NTH>>>(original, loc, conf, mask, proto, out);
}

// round 17
// speedup vs baseline: 1.2106x; 1.2106x over previous
#include <cuda_runtime.h>
#include <math.h>
#include <float.h>

#define B    2
#define P    19248
#define NC   100
#define NK   20
#define HP   138
#define HIMG 550
#define DM   32
#define CAND 1024
#define NBLK 148
#define NTH  1024
#define SF   (138.0f/550.0f)
#define THR0 0.96f
#define MAXFR 5
#define MAXYR 4
#define NPAIR (NC*(NC-1)/2)       /* 4950 */
#define A1C  (2*NC-1)             /* 199 */

__device__ unsigned long long d_cand[B*CAND];
__device__ unsigned d_candcnt[B];
__device__ float d_iou[B*NC*NC];
__device__ __align__(16) unsigned d_ioumax[B*NC];   // float-as-uint max, values >= 0
__device__ float d_ae[B];
__device__ double d_var_part[8];
__device__ unsigned d_done;
__device__ unsigned bar_count;
__device__ volatile unsigned bar_gen;

// grid-wide barrier: grid(148) <= #SMs, 1 block/SM => all co-resident.
__device__ __forceinline__ void gridsync() {
    __syncthreads();
    if (threadIdx.x == 0) {
        __threadfence();
        unsigned gen = bar_gen;
        unsigned arrived = atomicAdd(&bar_count, 1u);
        if (arrived == (unsigned)gridDim.x - 1u) {
            bar_count = 0u;
            __threadfence();
            bar_gen = gen + 1u;
        } else {
            while (bar_gen == gen) { }
            __threadfence();
        }
    }
    __syncthreads();
}

__device__ __forceinline__ void l2prefetch(const void* p) {
    asm volatile("prefetch.global.L2 [%0];" :: "l"(p));
}

// triangular pair decode: t in [0, NPAIR) -> (i, j), j > i
__device__ __forceinline__ void pairDecode(int t, int& i, int& j) {
    int ii = (int)(((float)A1C - sqrtf((float)(A1C*A1C) - 8.0f*(float)t)) * 0.5f);
    if (ii < 0) ii = 0;
    if (ii > NC-2) ii = NC-2;
    while (ii > 0 && ii*(A1C-ii)/2 > t) --ii;
    while (ii < NC-2 && (ii+1)*(A1C-(ii+1))/2 <= t) ++ii;
    i = ii;
    j = ii + 1 + (t - ii*(A1C-ii)/2);
}

__global__ void __launch_bounds__(NTH, 1)
fusedK(const float* __restrict__ original, const float* __restrict__ loc,
       const float* __restrict__ conf, const float* __restrict__ mask,
       const float* __restrict__ proto, float* __restrict__ out)
{
    __shared__ __align__(16) union {
        struct { unsigned long long cand[CAND]; } a2;
        struct { float ax[NC*32]; float ay[NC*32]; float gsum[NC]; float loc4[NC*4]; } b;
        struct { float m[2*NC]; } c;
        struct { float fc[2*MAXFR*HP]; float vrow[2*MAXYR*HP]; } d;
    } u;
    __shared__ float s_top_conf[B*NC];
    __shared__ int   s_top_idx[B*NC];
    __shared__ __align__(16) float s_km[B*NK*DM];
    __shared__ float s_kl[B*NK*4];
    __shared__ float s_krw[B*NK*2];
    __shared__ float s_kc[B*NK];
    __shared__ int   s_keep[B*NK];
    __shared__ float s_red[32];

    const int tid  = threadIdx.x;
    const int warp = tid >> 5, lane = tid & 31;
    const int bid  = blockIdx.x;
    const int bb   = bid & 1;            // this block's batch for phase B

    // ===== Phase A: fixed-threshold compact (32 blocks, 16 chunks/batch); rest prefetch =====
    if (bid < 32) {
        int b = bid & 1, chunk = bid >> 1;
        int p0c = (chunk * P) >> 4, p1c = ((chunk + 1) * P) >> 4;
        for (int p = p0c + tid; p < p1c; p += NTH) {
            float2 c2 = *(const float2*)(conf + (size_t)(b*P + p)*2);
            float v = 1.0f / (1.0f + expf(c2.x - c2.y));
            if (v >= THR0) {
                unsigned pos = atomicAdd(&d_candcnt[b], 1u);
                if (pos < CAND)
                    d_cand[b*CAND + pos] = ((unsigned long long)__float_as_uint(v) << 32)
                                         | (unsigned long long)(0xFFFFFFFFu - (unsigned)p);
            }
        }
    } else {
        // prefetch original (7.26MB) + proto (4.87MB) + loc (0.31MB) into L2
        const size_t lines1 = ((size_t)B*3*HIMG*HIMG*4) >> 7;
        const size_t lines2 = ((size_t)B*HP*HP*DM*4) >> 7;
        const size_t lines3 = ((size_t)B*P*4*4) >> 7;
        size_t start = (size_t)(bid - 32) * NTH + tid;
        size_t stride = (size_t)(NBLK - 32) * NTH;
        const char* o = (const char*)original;
        const char* q = (const char*)proto;
        const char* l = (const char*)loc;
        for (size_t i = start; i < lines1; i += stride) l2prefetch(o + (i << 7));
        for (size_t i = start; i < lines2; i += stride) l2prefetch(q + (i << 7));
        for (size_t i = start; i < lines3; i += stride) l2prefetch(l + (i << 7));
    }
    gridsync();

    // ===== Phase A2b: redundant rank on EVERY block (both batches, cheap) =====
    for (int cb = 0; cb < B; cb++) {
        unsigned cntu = d_candcnt[cb];
        if (cntu >= NC && cntu <= CAND) {
            int cnt = (int)cntu;
            for (int i = tid; i < cnt; i += NTH) u.a2.cand[i] = d_cand[cb*CAND + i];
            __syncthreads();
            if (tid < cnt) {
                unsigned long long mykey = u.a2.cand[tid];
                int rank = 0;
                #pragma unroll 4
                for (int c2 = 0; c2 < cnt; c2++)
                    rank += (u.a2.cand[c2] > mykey) ? 1 : 0;
                if (rank < NC) {
                    s_top_conf[cb*NC + rank] = __uint_as_float((unsigned)(mykey >> 32));
                    s_top_idx[cb*NC + rank]  = (int)(0xFFFFFFFFu - (unsigned)(mykey & 0xFFFFFFFFull));
                }
            }
            __syncthreads();
        } else {
            // fallback: redundant non-destructive iterative top-100, sigmoid recomputed
            unsigned long long prev = 0xFFFFFFFFFFFFFFFFull;
            for (int it = 0; it < NC; it++) {
                unsigned long long best = 0ull;
                for (int p = tid; p < P; p += NTH) {
                    float2 c2 = *(const float2*)(conf + (size_t)(cb*P + p)*2);
                    float v = 1.0f / (1.0f + expf(c2.x - c2.y));
                    unsigned long long key = ((unsigned long long)__float_as_uint(v) << 32)
                                           | (unsigned long long)(0xFFFFFFFFu - (unsigned)p);
                    if (key < prev && key > best) best = key;
                }
                #pragma unroll
                for (int off = 16; off > 0; off >>= 1) {
                    unsigned long long o = __shfl_down_sync(0xffffffffu, best, off);
                    if (o > best) best = o;
                }
                if (lane == 0) u.a2.cand[warp] = best;
                __syncthreads();
                if (tid < 32) {
                    best = u.a2.cand[tid];
                    #pragma unroll
                    for (int off = 16; off > 0; off >>= 1) {
                        unsigned long long o = __shfl_down_sync(0xffffffffu, best, off);
                        if (o > best) best = o;
                    }
                    if (tid == 0) {
                        s_top_conf[cb*NC + it] = __uint_as_float((unsigned)(best >> 32));
                        s_top_idx[cb*NC + it]  = (int)(0xFFFFFFFFu - (unsigned)(best & 0xFFFFFFFFull));
                        u.a2.cand[0] = best;
                    }
                }
                __syncthreads();
                prev = u.a2.cand[0];
                __syncthreads();
            }
        }
    }

    // ===== Phase B: pairwise IoU for batch bb, 74-block pair partitions =====
    {
        if (tid < NC*4) {
            int box = tid >> 2, c = tid & 3;
            int gi = s_top_idx[bb*NC + box];
            u.b.loc4[tid] = loc[((size_t)bb*P + gi)*4 + c];
        }
        __syncthreads();
        for (int t = tid; t < NC*32; t += NTH) {
            int box = t >> 5, e = t & 31;
            float s = (e + 0.5f) / 32.0f;
            float dx = (s - u.b.loc4[box*4+0]) / (u.b.loc4[box*4+2] + 1e-4f);
            float dy = (s - u.b.loc4[box*4+1]) / (u.b.loc4[box*4+3] + 1e-4f);
            u.b.ax[t] = expf(-0.5f * dx * dx);
            u.b.ay[t] = expf(-0.5f * dy * dy);
        }
        __syncthreads();
        if (tid < NC) {
            float sx = 0.f, sy = 0.f;
            #pragma unroll
            for (int e = 0; e < 32; e++) { sx += u.b.ax[tid*32+e]; sy += u.b.ay[tid*32+e]; }
            u.b.gsum[tid] = sx * sy;
        }
        __syncthreads();
        const int pb = bid >> 1;                 // 0..73 within batch partition
        for (int t = pb*32 + warp; t < NPAIR; t += 74*32) {
            int i, j;
            pairDecode(t, i, j);
            float gix = u.b.ax[i*32 + lane];
            float axj = u.b.ax[j*32 + lane];
            float acc = 0.f;
            #pragma unroll
            for (int y = 0; y < 32; y++)
                acc += fminf(u.b.ay[i*32 + y] * gix, u.b.ay[j*32 + y] * axj);
            #pragma unroll
            for (int off = 16; off > 0; off >>= 1)
                acc += __shfl_down_sync(0xffffffffu, acc, off);
            if (lane == 0) {
                float denom = u.b.gsum[i] + u.b.gsum[j] - acc;
                float iouv = acc / denom;
                d_iou[(bb*NC + i)*NC + j] = iouv;
                atomicMax(&d_ioumax[bb*NC + j], __float_as_uint(iouv));
            }
        }
    }
    gridsync();

    // ===== Phase C: keep-20 + gathers (all blocks, cheap); AE on blocks 0,1 =====
    {
        // reset d_candcnt (consumed in A2b before the barrier)
        if (bid == 0 && tid < B) d_candcnt[tid] = 0u;
        // col-max precomputed via atomicMax in B
        if (tid < 2*NC) u.c.m[tid] = __uint_as_float(d_ioumax[tid]);
        __syncthreads();
        // rank-by-counting ascending (m, j)
        if (tid < 2*NC) {
            int cb = tid / NC, j = tid % NC;
            float m = u.c.m[tid];
            int rank = 0;
            #pragma unroll 4
            for (int j2 = 0; j2 < NC; j2++) {
                float m2 = u.c.m[cb*NC + j2];
                rank += (m2 < m || (m2 == m && j2 < j)) ? 1 : 0;
            }
            if (rank < NK) s_keep[cb*NK + rank] = j;
        }
        __syncthreads();
        if (tid < B*NK) {
            int cb = tid / NK;
            int j = s_keep[tid];
            int gi = s_top_idx[cb*NC + j];
            s_kc[tid] = s_top_conf[cb*NC + j];
            #pragma unroll
            for (int c = 0; c < 4; c++)
                s_kl[tid*4 + c] = loc[((size_t)cb*P + gi)*4 + c];
            s_krw[tid*2 + 0] = 1.0f / (s_kl[tid*4 + 2] + 1e-4f);
            s_krw[tid*2 + 1] = 1.0f / (s_kl[tid*4 + 3] + 1e-4f);
        }
        __syncthreads();
        for (int t = tid; t < B*NK*DM; t += NTH) {
            int cb = t / (NK*DM);
            int k = (t / DM) % NK, c = t % DM;
            int gi = s_top_idx[cb*NC + s_keep[cb*NK + k]];
            s_km[t] = mask[((size_t)cb*P + gi)*DM + c];
        }
        __syncthreads();
        if (bid < B) {
            int b = bid;
            float acc = 0.f;
            for (int t = tid; t < NK*NC; t += NTH) {
                int k = t / NC, j = t % NC;
                int ik = s_keep[b*NK + k];
                if (j > ik) {
                    float l0 = s_kl[(b*NK + k)*4 + 0], l1 = s_kl[(b*NK + k)*4 + 1];
                    float l2 = s_kl[(b*NK + k)*4 + 2], l3 = s_kl[(b*NK + k)*4 + 3];
                    float ael = 0.25f * (l0*l0 + l1*l1 + l2*l2 + l3*l3);
                    acc += ael * s_top_conf[b*NC + ik] * s_top_conf[b*NC + j]
                               * d_iou[(b*NC + ik)*NC + j];
                }
            }
            #pragma unroll
            for (int off = 16; off > 0; off >>= 1) acc += __shfl_down_sync(0xffffffffu, acc, off);
            if (lane == 0) s_red[warp] = acc;
            __syncthreads();
            if (tid < 32) {
                acc = s_red[tid];
                #pragma unroll
                for (int off = 16; off > 0; off >>= 1) acc += __shfl_down_sync(0xffffffffu, acc, off);
                if (tid == 0) d_ae[b] = acc / (float)(B*NC*NC);
            }
        }
        __syncthreads();
    }

    // ===== Phase D: per-strip fconf + separable bilinear + variance (R12 form) =====
    {
        int y0 = bid * HIMG / NBLK, y1 = (bid + 1) * HIMG / NBLK;
        float fyMin = (y0 + 0.5f)*SF - 0.5f;
        float fyMax = (y1 - 0.5f)*SF - 0.5f;
        int fr0 = max((int)floorf(fyMin), 0);
        int fr1 = min((int)floorf(fyMax) + 1, HP-1);
        int nfr = fr1 - fr0 + 1;                      // <= MAXFR
        for (int t = tid; t < B*nfr*HP; t += NTH) {
            int b = t / (nfr*HP);
            int r = (t / HP) % nfr;
            int w = t % HP;
            int fh = fr0 + r;
            const float4* pr4 = (const float4*)(proto + ((size_t)(b*HP + fh)*HP + w) * DM);
            const float4* km4 = (const float4*)(s_km + b*NK*DM);
            float acc[NK];
            #pragma unroll
            for (int k = 0; k < NK; k++) acc[k] = 0.f;
            #pragma unroll
            for (int c4 = 0; c4 < 8; c4++) {
                float4 p4 = pr4[c4];
                #pragma unroll
                for (int k = 0; k < NK; k++) {
                    float4 m4 = km4[k*8 + c4];
                    acc[k] += p4.x*m4.x + p4.y*m4.y + p4.z*m4.z + p4.w*m4.w;
                }
            }
            float xs = (w + 0.5f) * (1.0f/(float)HP);
            float ys = (fh + 0.5f) * (1.0f/(float)HP);
            float s1 = 0.f, s2 = 0.f;
            #pragma unroll
            for (int k = 0; k < NK; k++) {
                float e = __expf(-acc[k]);
                float sig = __fdividef(1.0f, 1.0f + e);
                float cx = s_kl[(b*NK+k)*4+0], cy = s_kl[(b*NK+k)*4+1];
                float rw = s_krw[(b*NK+k)*2+0], rh = s_krw[(b*NK+k)*2+1];
                float dx = (xs - cx) * rw;
                float dy = (ys - cy) * rh;
                float g = __expf(-0.5f * (dx*dx + dy*dy));
                float mc = sig * g * s_kc[b*NK + k];
                s1 += mc;
                s2 = fmaf(mc, mc, s2);
            }
            float fc = 1.0f - __fdividef(s2, s1 + 1e-6f);
            if (fc != fc) fc = 0.f;
            u.d.fc[(b*MAXFR + r)*HP + w] = fc;
        }
        __syncthreads();
        // vertical interpolation rows: vrow[b][rr][xc], rr in [0, y1-y0)
        int nyr = y1 - y0;                            // <= MAXYR
        for (int t = tid; t < B*nyr*HP; t += NTH) {
            int b = t / (nyr*HP);
            int rr = (t / HP) % nyr;
            int xc = t % HP;
            int y = y0 + rr;
            float fy = (y + 0.5f)*SF - 0.5f;
            float fy0 = floorf(fy);
            float ty = fy - fy0;
            int yy0 = (int)fy0;
            int y0c = min(max(yy0, 0), HP-1), y1c = min(max(yy0+1, 0), HP-1);
            int r0i = y0c - fr0, r1i = y1c - fr0;
            const float* fb = &u.d.fc[b*MAXFR*HP];
            float a = fb[r0i*HP + xc], bv = fb[r1i*HP + xc];
            u.d.vrow[(b*MAXYR + rr)*HP + xc] = a + ty*(bv - a);
        }
        __syncthreads();
        float acc = 0.f;
        {
            int npix2 = (nyr * HIMG) >> 1;            // always even
            int gbase = y0 * HIMG;
            for (int idx2 = tid; idx2 < npix2; idx2 += NTH) {
                int g = gbase + (idx2 << 1);
                int y = g / HIMG, x = g - y * HIMG;   // x even, x+1 in same row
                int rr = y - y0;
                const float* v0 = &u.d.vrow[(0*MAXYR + rr)*HP];
                const float* v1 = &u.d.vrow[(1*MAXYR + rr)*HP];
                float rA0, rA1, rB0, rB1;
                #pragma unroll
                for (int px = 0; px < 2; px++) {
                    float fx = (x + px + 0.5f)*SF - 0.5f;
                    float fx0 = floorf(fx);
                    float tx = fx - fx0;
                    int x0 = (int)fx0;
                    int x0c = min(max(x0, 0), HP-1), x1c = min(max(x0+1, 0), HP-1);
                    float a0 = v0[x0c], b0 = v0[x1c];
                    float a1 = v1[x0c], b1 = v1[x1c];
                    float r0 = a0 + tx*(b0 - a0);
                    float r1 = a1 + tx*(b1 - a1);
                    if (px == 0) { rA0 = r0; rA1 = r1; } else { rB0 = r0; rB1 = r1; }
                }
                float totA = rA0 + rA1, totB = rB0 + rB1;
                float invA  = __fdividef(1.0f, totA);
                float invB  = __fdividef(1.0f, totB);
                float invAe = __fdividef(1.0f, totA + 1e-6f);
                float invBe = __fdividef(1.0f, totB + 1e-6f);
                #pragma unroll
                for (int c = 0; c < 3; c++) {
                    float2 o0 = *(const float2*)(original + (size_t)(0*3 + c)*HIMG*HIMG + g);
                    float2 o1 = *(const float2*)(original + (size_t)(1*3 + c)*HIMG*HIMG + g);
                    float wmA = (o0.x*rA0 + o1.x*rA1) * invA;
                    float dA0 = o0.x - wmA, dA1 = o1.x - wmA;
                    acc += (dA0*dA0*rA0 + dA1*dA1*rA1) * invAe;
                    float wmB = (o0.y*rB0 + o1.y*rB1) * invB;
                    float dB0 = o0.y - wmB, dB1 = o1.y - wmB;
                    acc += (dB0*dB0*rB0 + dB1*dB1*rB1) * invBe;
                }
            }
        }
        #pragma unroll
        for (int off = 16; off > 0; off >>= 1) acc += __shfl_down_sync(0xffffffffu, acc, off);
        if (lane == 0) s_red[warp] = acc;
        __syncthreads();
        if (tid < 32) {
            acc = s_red[tid];
            #pragma unroll
            for (int off = 16; off > 0; off >>= 1) acc += __shfl_down_sync(0xffffffffu, acc, off);
            if (tid == 0) {
                atomicAdd(&d_var_part[bid & 7], (double)acc);
                __threadfence();
                unsigned ticket = atomicAdd(&d_done, 1u);
                if (ticket == (unsigned)gridDim.x - 1u) {
                    __threadfence();
                    double vs = 0.0;
                    #pragma unroll
                    for (int i = 0; i < 8; i++) { vs += d_var_part[i]; d_var_part[i] = 0.0; }
                    out[0] = (float)(vs / (double)HP * (double)B);
                    out[1] = d_ae[0] + d_ae[1];
                    uint4 z = make_uint4(0u, 0u, 0u, 0u);
                    for (int i = 0; i < (B*NC)/4; i++)           // reset for replay
                        ((uint4*)d_ioumax)[i] = z;
                    d_done = 0u;
                }
            }
        }
    }
}

extern "C" void kernel_launch(void* const* d_in, const int* in_sizes, int n_in,
                              void* d_out, int out_size) {
    const float* original = (const float*)d_in[0];
    const float* loc      = (const float*)d_in[1];
    const float* conf     = (const float*)d_in[2];
    const float* mask     = (const float*)d_in[3];
    const float* proto    = (const float*)d_in[4];
    float* out = (float*)d_out;

    fusedK<<<NBLK, NTH>>>(original, loc, conf, mask, proto, out);
}